// round 10
// baseline (speedup 1.0000x reference)
#include <cuda_runtime.h>
#include <cuda_bf16.h>
#include <cstdint>

#define DEV __device__ __forceinline__
DEV float sigm(float x){ return 1.0f/(1.0f+__expf(-x)); }
DEV float ftanh(float x){ return 1.0f - 2.0f/(__expf(2.0f*x)+1.0f); }
DEV float tanha(float x){ float r; asm("tanh.approx.f32 %0, %1;" : "=f"(r) : "f"(x)); return r; }
DEV unsigned swz(unsigned off){ return off ^ ((off>>3)&0x70); }

// dims: B=64,S=50,T=50,U=1024,E=256,VT=16000,G3=3072
constexpr long O_ENCGI = 0;                      // 3200x3072 row=t*64+b
constexpr long O_DEMB  = O_ENCGI + 9830400L;     // 3136x3072 row=t*64+b
constexpr long O_PART  = O_DEMB  + 9633792L;     // 4 x 64x3072 split-K partials
constexpr long O_QPART = O_PART  + 786432L;      // 4 x 64x1024
constexpr long O_HF    = O_QPART + 262144L;      // 64x1024 f32 enc h
constexpr long O_NLL   = O_HF    + 65536L;       // 3136
constexpr long SCRATCH_TOTAL = O_NLL + 3200L;

__device__ __align__(16) float g_scratch[SCRATCH_TOTAL];
__device__ int g_didx[3136];
__device__ int g_eidx[3200];
__device__ int g_cnt[16];          // zero-init; each fused kernel leaves them zero

__device__ __align__(16) __nv_bfloat16 g_fcWb[16384000];
__device__ __align__(16) __nv_bfloat16 g_encWhb[3145728];
__device__ __align__(16) __nv_bfloat16 g_W1b[1048576];
__device__ __align__(16) __nv_bfloat16 g_decWxb[3145728];
__device__ __align__(16) __nv_bfloat16 g_decWxb2[786432];
__device__ __align__(16) __nv_bfloat16 g_encWxb[786432];
__device__ __align__(16) __nv_bfloat16 g_W2b[1048576];
__device__ __align__(16) __nv_bfloat16 g_encEmbb[3072000];
__device__ __align__(16) __nv_bfloat16 g_decEmbb[4096000];
__device__ __align__(16) __nv_bfloat16 g_h0[65536];
__device__ __align__(16) __nv_bfloat16 g_h1[65536];
__device__ __align__(16) __nv_bfloat16 g_ctxb[65536];
__device__ __align__(16) __nv_bfloat16 g_eob[3276800];     // row=b*50+t
__device__ __align__(16) __nv_bfloat16 g_keysb[3276800];
__device__ __align__(16) __nv_bfloat16 g_hallb[3211264];   // row=t*64+b
__device__ __align__(16) __nv_bfloat16 g_logitsb[50176000];

__global__ void setup_all(const int* __restrict__ inp, const int* __restrict__ targ,
                          const float* __restrict__ hsrc, float* __restrict__ hf,
                          __nv_bfloat16* __restrict__ hb){
    int i = blockIdx.x*256 + threadIdx.x;
    if (i < 65536){ float v = hsrc[i]; hf[i] = v; hb[i] = __float2bfloat16(v); }
    if (i < 3136){ int t = i >> 6, b = i & 63; g_didx[i] = targ[b*50 + t]; }
    if (i < 3200){ int t = i >> 6, b = i & 63; g_eidx[i] = inp[b*50 + t]; }
    if (i < 16) g_cnt[i] = 0;
}
__global__ void cvt_bf16(__nv_bfloat16* __restrict__ dst, const float* __restrict__ src, long n){
    long i = ((long)blockIdx.x*256 + threadIdx.x)*4;
    if (i < n){
        float4 v = *reinterpret_cast<const float4*>(src + i);
        __nv_bfloat162 lo = __floats2bfloat162_rn(v.x, v.y);
        __nv_bfloat162 hi = __floats2bfloat162_rn(v.z, v.w);
        uint2 o; o.x = *reinterpret_cast<unsigned*>(&lo); o.y = *reinterpret_cast<unsigned*>(&hi);
        *reinterpret_cast<uint2*>(dst + i) = o;
    }
}

// ---- general 64x64 mma GEMM, gather A, f32/bf16 out (R6-proven) ----
__global__ __launch_bounds__(256) void gemm_mma(
    const __nv_bfloat16* __restrict__ A, int lda, const int* __restrict__ gidx,
    const __nv_bfloat16* __restrict__ Bm, int ldb, const float* __restrict__ bias,
    float* __restrict__ C, __nv_bfloat16* __restrict__ Cb, int ldc, int K)
{
    __shared__ __align__(16) char smA[2][8192];
    __shared__ __align__(16) char smB[2][8192];
    const int tid = threadIdx.x, warp = tid >> 5, lane = tid & 31;
    const int wm = warp >> 2, wn = warp & 3;
    const int row0 = blockIdx.y << 6, col0 = blockIdx.x << 6;
    unsigned sA[2] = { (unsigned)__cvta_generic_to_shared(smA[0]), (unsigned)__cvta_generic_to_shared(smA[1]) };
    unsigned sB[2] = { (unsigned)__cvta_generic_to_shared(smB[0]), (unsigned)__cvta_generic_to_shared(smB[1]) };
    float acc[2][2][4] = {};
    const int lr = tid >> 3, lc = tid & 7;
    long ar0 = gidx ? (long)gidx[row0+lr]*lda    : (long)(row0+lr)*lda;
    long ar1 = gidx ? (long)gidx[row0+lr+32]*lda : (long)(row0+lr+32)*lda;
    auto issue = [&](int st, int k0){
        asm volatile("cp.async.cg.shared.global [%0], [%1], 16;"
            :: "r"(sA[st] + swz(lr*128 + lc*16)), "l"(A + ar0 + k0 + lc*8));
        asm volatile("cp.async.cg.shared.global [%0], [%1], 16;"
            :: "r"(sA[st] + swz((lr+32)*128 + lc*16)), "l"(A + ar1 + k0 + lc*8));
        #pragma unroll
        for (int i=0;i<2;i++){
            int r = lr + i*32;
            asm volatile("cp.async.cg.shared.global [%0], [%1], 16;"
                :: "r"(sB[st] + swz(r*128 + lc*16)), "l"(Bm + (long)(k0+r)*ldb + col0 + lc*8));
        }
        asm volatile("cp.async.commit_group;");
    };
    const int nk = K >> 6;
    issue(0, 0);
    for (int kt = 0; kt < nk; kt++){
        if (kt + 1 < nk){ issue((kt+1)&1, (kt+1)<<6); asm volatile("cp.async.wait_group 1;" ::: "memory"); }
        else asm volatile("cp.async.wait_group 0;" ::: "memory");
        __syncthreads();
        const int st = kt & 1;
        #pragma unroll
        for (int ks = 0; ks < 4; ks++){
            unsigned a[2][4];
            #pragma unroll
            for (int mt = 0; mt < 2; mt++){
                int r = wm*32 + mt*16 + (lane & 15), c = ks*16 + (lane >> 4)*8;
                asm volatile("ldmatrix.sync.aligned.m8n8.x4.shared.b16 {%0,%1,%2,%3}, [%4];"
                    : "=r"(a[mt][0]),"=r"(a[mt][1]),"=r"(a[mt][2]),"=r"(a[mt][3])
                    : "r"(sA[st] + swz(r*128 + c*2)));
            }
            unsigned b[4];
            int kk = ks*16 + ((lane>>3)&1)*8 + (lane & 7), nn = wn*16 + (lane>>4)*8;
            asm volatile("ldmatrix.sync.aligned.m8n8.x4.trans.shared.b16 {%0,%1,%2,%3}, [%4];"
                : "=r"(b[0]),"=r"(b[1]),"=r"(b[2]),"=r"(b[3])
                : "r"(sB[st] + swz(kk*128 + nn*2)));
            #pragma unroll
            for (int mt = 0; mt < 2; mt++)
                #pragma unroll
                for (int nt = 0; nt < 2; nt++){
                    float* d = acc[mt][nt];
                    asm volatile("mma.sync.aligned.m16n8k16.row.col.f32.bf16.bf16.f32 "
                        "{%0,%1,%2,%3}, {%4,%5,%6,%7}, {%8,%9}, {%0,%1,%2,%3};"
                        : "+f"(d[0]),"+f"(d[1]),"+f"(d[2]),"+f"(d[3])
                        : "r"(a[mt][0]),"r"(a[mt][1]),"r"(a[mt][2]),"r"(a[mt][3]),
                          "r"(b[nt*2]),"r"(b[nt*2+1]));
                }
        }
        __syncthreads();
    }
    const int rb = row0 + wm*32 + (lane>>2), cb = col0 + wn*16 + (lane&3)*2;
    #pragma unroll
    for (int nt = 0; nt < 2; nt++){
        int cc = cb + nt*8;
        float bv0 = bias ? bias[cc] : 0.f, bv1 = bias ? bias[cc+1] : 0.f;
        #pragma unroll
        for (int mt = 0; mt < 2; mt++){
            int r = rb + mt*16;
            float x0 = acc[mt][nt][0]+bv0, x1 = acc[mt][nt][1]+bv1;
            float y0 = acc[mt][nt][2]+bv0, y1 = acc[mt][nt][3]+bv1;
            if (C){
                *reinterpret_cast<float2*>(&C[(long)r*ldc + cc]) = make_float2(x0, x1);
                *reinterpret_cast<float2*>(&C[(long)(r+8)*ldc + cc]) = make_float2(y0, y1);
            }
            if (Cb){
                *reinterpret_cast<__nv_bfloat162*>(&Cb[(long)r*ldc + cc]) = __floats2bfloat162_rn(x0, x1);
                *reinterpret_cast<__nv_bfloat162*>(&Cb[(long)(r+8)*ldc + cc]) = __floats2bfloat162_rn(y0, y1);
            }
        }
    }
}

// ---- split-K microkernel body: acc = A[64 x Kslice] @ B[Kslice x 64cols] ----
DEV void splitk_body(char* smem, const __nv_bfloat16* __restrict__ A, int lda,
                     const __nv_bfloat16* __restrict__ Bm, int ldb,
                     int col0, int kbeg, int nk,
                     float acc[2][2][4], int tid, int wm, int wn, int lane)
{
    unsigned base = (unsigned)__cvta_generic_to_shared(smem);
    const int lr = tid >> 3, lc = tid & 7;
    auto issue = [&](int st, int k0){
        unsigned sA = base + st*16384, sB = sA + 8192;
        asm volatile("cp.async.cg.shared.global [%0], [%1], 16;"
            :: "r"(sA + swz(lr*128 + lc*16)), "l"(A + (long)lr*lda + kbeg + k0 + lc*8));
        asm volatile("cp.async.cg.shared.global [%0], [%1], 16;"
            :: "r"(sA + swz((lr+32)*128 + lc*16)), "l"(A + (long)(lr+32)*lda + kbeg + k0 + lc*8));
        #pragma unroll
        for (int i=0;i<2;i++){
            int r = lr + i*32;
            asm volatile("cp.async.cg.shared.global [%0], [%1], 16;"
                :: "r"(sB + swz(r*128 + lc*16)), "l"(Bm + (long)(kbeg+k0+r)*ldb + col0 + lc*8));
        }
        asm volatile("cp.async.commit_group;");
    };
    issue(0, 0);
    for (int kt = 0; kt < nk; kt++){
        if (kt + 1 < nk){ issue((kt+1)&1, (kt+1)<<6); asm volatile("cp.async.wait_group 1;" ::: "memory"); }
        else asm volatile("cp.async.wait_group 0;" ::: "memory");
        __syncthreads();
        unsigned sA = base + (kt&1)*16384, sB = sA + 8192;
        #pragma unroll
        for (int ks = 0; ks < 4; ks++){
            unsigned a[2][4];
            #pragma unroll
            for (int mt = 0; mt < 2; mt++){
                int r = wm*32 + mt*16 + (lane & 15), c = ks*16 + (lane >> 4)*8;
                asm volatile("ldmatrix.sync.aligned.m8n8.x4.shared.b16 {%0,%1,%2,%3}, [%4];"
                    : "=r"(a[mt][0]),"=r"(a[mt][1]),"=r"(a[mt][2]),"=r"(a[mt][3])
                    : "r"(sA + swz(r*128 + c*2)));
            }
            unsigned b[4];
            int kk = ks*16 + ((lane>>3)&1)*8 + (lane & 7), nn = wn*16 + (lane>>4)*8;
            asm volatile("ldmatrix.sync.aligned.m8n8.x4.trans.shared.b16 {%0,%1,%2,%3}, [%4];"
                : "=r"(b[0]),"=r"(b[1]),"=r"(b[2]),"=r"(b[3])
                : "r"(sB + swz(kk*128 + nn*2)));
            #pragma unroll
            for (int mt = 0; mt < 2; mt++)
                #pragma unroll
                for (int nt = 0; nt < 2; nt++){
                    float* d = acc[mt][nt];
                    asm volatile("mma.sync.aligned.m16n8k16.row.col.f32.bf16.bf16.f32 "
                        "{%0,%1,%2,%3}, {%4,%5,%6,%7}, {%8,%9}, {%0,%1,%2,%3};"
                        : "+f"(d[0]),"+f"(d[1]),"+f"(d[2]),"+f"(d[3])
                        : "r"(a[mt][0]),"r"(a[mt][1]),"r"(a[mt][2]),"r"(a[mt][3]),
                          "r"(b[nt*2]),"r"(b[nt*2+1]));
                }
        }
        __syncthreads();
    }
}

DEV void store_partial(float* Cout, int N, int col0, float acc[2][2][4], int wm, int wn, int lane){
    const int rb = wm*32 + (lane>>2), cb = col0 + wn*16 + (lane&3)*2;
    #pragma unroll
    for (int nt = 0; nt < 2; nt++){
        int cc = cb + nt*8;
        #pragma unroll
        for (int mt = 0; mt < 2; mt++){
            int r = rb + mt*16;
            *reinterpret_cast<float2*>(&Cout[(long)r*N + cc]) = make_float2(acc[mt][nt][0], acc[mt][nt][1]);
            *reinterpret_cast<float2*>(&Cout[(long)(r+8)*N + cc]) = make_float2(acc[mt][nt][2], acc[mt][nt][3]);
        }
    }
}

// ---- q split-K (decoder phase 1): grid (16,4) ----
__global__ __launch_bounds__(256) void gemm_splitk_q(
    const __nv_bfloat16* __restrict__ A, const __nv_bfloat16* __restrict__ Bm,
    float* __restrict__ C)
{
    __shared__ __align__(16) char smem[32768];
    const int tid = threadIdx.x, warp = tid >> 5, lane = tid & 31;
    const int wm = warp >> 2, wn = warp & 3;
    float acc[2][2][4] = {};
    splitk_body(smem, A, 1024, Bm, 1024, blockIdx.x<<6, blockIdx.y*256, 4, acc, tid, wm, wn, lane);
    store_partial(C + (long)blockIdx.y*65536, 1024, blockIdx.x<<6, acc, wm, wn, lane);
}

// ---- FUSED encoder step: split-K gates GEMM + last-of-12 GRU combine. grid (48,4) ----
__global__ __launch_bounds__(256) void enc_step(
    int t, const __nv_bfloat16* __restrict__ hin, const __nv_bfloat16* __restrict__ Whb,
    const float* __restrict__ encgi, const float* __restrict__ encb2,
    float* __restrict__ part, float* __restrict__ hf,
    __nv_bfloat16* __restrict__ hout, __nv_bfloat16* __restrict__ eob)
{
    __shared__ __align__(16) char smem[32768];
    __shared__ int s_old;
    const int tid = threadIdx.x, warp = tid >> 5, lane = tid & 31;
    const int wm = warp >> 2, wn = warp & 3;
    const int cx = blockIdx.x, col0 = cx << 6;
    float acc[2][2][4] = {};
    splitk_body(smem, hin, 1024, Whb, 3072, col0, blockIdx.y*256, 4, acc, tid, wm, wn, lane);
    store_partial(part + (long)blockIdx.y*196608, 3072, col0, acc, wm, wn, lane);
    __threadfence();
    __syncthreads();
    const int j = cx & 15;
    if (tid == 0) s_old = atomicAdd(&g_cnt[j], 1);
    __syncthreads();
    if (s_old == 11){
        __threadfence();
        const int PS = 196608;
        #pragma unroll
        for (int it = 0; it < 16; it++){
            int idx = it*256 + tid;
            int b = idx >> 6, uc = idx & 63;
            int u = j*64 + uc;
            long p = (long)b*3072 + u;
            long gi = (long)(t*64 + b)*3072 + u;
            float ghz = part[p]      + part[PS+p]      + part[2*PS+p]      + part[3*PS+p]      + encb2[u];
            float ghr = part[p+1024] + part[PS+p+1024] + part[2*PS+p+1024] + part[3*PS+p+1024] + encb2[1024+u];
            float ghh = part[p+2048] + part[PS+p+2048] + part[2*PS+p+2048] + part[3*PS+p+2048] + encb2[2048+u];
            float z = sigm(encgi[gi] + ghz);
            float r = sigm(encgi[gi+1024] + ghr);
            float hc = ftanh(encgi[gi+2048] + r*ghh);
            int hidx = b*1024 + u;
            float hn = z*hf[hidx] + (1.0f - z)*hc;
            hf[hidx] = hn;
            __nv_bfloat16 hv = __float2bfloat16(hn);
            hout[hidx] = hv;
            eob[(long)(b*50 + t)*1024 + u] = hv;
        }
        __syncthreads();
        if (tid == 0) g_cnt[j] = 0;
    }
}

// ---- FUSED decoder gates step (h==0): grid (48,4) ----
__global__ __launch_bounds__(256) void dec_step(
    int t, const __nv_bfloat16* __restrict__ ctxb, const __nv_bfloat16* __restrict__ Wxb,
    const float* __restrict__ dembgi, const float* __restrict__ decb2,
    float* __restrict__ part, __nv_bfloat16* __restrict__ hb, __nv_bfloat16* __restrict__ hallb)
{
    __shared__ __align__(16) char smem[32768];
    __shared__ int s_old;
    const int tid = threadIdx.x, warp = tid >> 5, lane = tid & 31;
    const int wm = warp >> 2, wn = warp & 3;
    const int cx = blockIdx.x, col0 = cx << 6;
    float acc[2][2][4] = {};
    splitk_body(smem, ctxb, 1024, Wxb, 3072, col0, blockIdx.y*256, 4, acc, tid, wm, wn, lane);
    store_partial(part + (long)blockIdx.y*196608, 3072, col0, acc, wm, wn, lane);
    __threadfence();
    __syncthreads();
    const int j = cx & 15;
    if (tid == 0) s_old = atomicAdd(&g_cnt[j], 1);
    __syncthreads();
    if (s_old == 11){
        __threadfence();
        const int PS = 196608;
        #pragma unroll
        for (int it = 0; it < 16; it++){
            int idx = it*256 + tid;
            int b = idx >> 6, uc = idx & 63;
            int u = j*64 + uc;
            long p = (long)b*3072 + u;
            long gi = (long)(t*64 + b)*3072 + u;
            float gz = part[p]      + part[PS+p]      + part[2*PS+p]      + part[3*PS+p];
            float gr = part[p+1024] + part[PS+p+1024] + part[2*PS+p+1024] + part[3*PS+p+1024];
            float gh = part[p+2048] + part[PS+p+2048] + part[2*PS+p+2048] + part[3*PS+p+2048];
            float z = sigm(dembgi[gi] + gz + decb2[u]);
            float r = sigm(dembgi[gi+1024] + gr + decb2[1024+u]);
            float hc = ftanh(dembgi[gi+2048] + gh + r*decb2[2048+u]);
            float hn = (1.0f - z)*hc;
            __nv_bfloat16 hv = __float2bfloat16(hn);
            hb[b*1024 + u] = hv;
            hallb[(long)(t*64 + b)*1024 + u] = hv;
        }
        __syncthreads();
        if (tid == 0) g_cnt[j] = 0;
    }
}

// ---- fc GEMM: BM=128 BN=128 BK=64, bf16 out (R7 math, verified) ----
__global__ __launch_bounds__(256) void gemm_fc(
    const __nv_bfloat16* __restrict__ A, const __nv_bfloat16* __restrict__ Bm,
    const float* __restrict__ bias, __nv_bfloat16* __restrict__ Cb)
{
    extern __shared__ char sm[];
    const int tid = threadIdx.x, warp = tid >> 5, lane = tid & 31;
    const int wm = warp >> 2, wn = warp & 3;
    const int row0 = blockIdx.y << 7, col0 = blockIdx.x << 7;
    unsigned base = (unsigned)__cvta_generic_to_shared(sm);
    float acc[4][4][4] = {};
    auto issue = [&](int st, int k0){
        unsigned sA = base + st*32768, sB = sA + 16384;
        int r = tid>>3, c8 = tid&7;
        #pragma unroll
        for (int i=0;i<4;i++){
            int rr = r + i*32;
            int rg = row0 + rr; if (rg > 3135) rg = 3135;
            asm volatile("cp.async.cg.shared.global [%0], [%1], 16;"
                :: "r"(sA + swz(rr*128 + c8*16)), "l"(A + (long)rg*1024 + k0 + c8*8));
        }
        #pragma unroll
        for (int p=0;p<4;p++){
            int idx = p*256 + tid;
            int rr = idx>>4, c16 = idx&15;
            int panel = c16>>3, cp = c16&7;
            asm volatile("cp.async.cg.shared.global [%0], [%1], 16;"
                :: "r"(sB + panel*8192 + swz(rr*128 + cp*16)),
                   "l"(Bm + (long)(k0+rr)*16000 + col0 + c16*8));
        }
        asm volatile("cp.async.commit_group;");
    };
    issue(0, 0);
    for (int kt = 0; kt < 16; kt++){
        if (kt+1 < 16){ issue((kt+1)&1, (kt+1)<<6); asm volatile("cp.async.wait_group 1;" ::: "memory"); }
        else asm volatile("cp.async.wait_group 0;" ::: "memory");
        __syncthreads();
        unsigned sA = base + (kt&1)*32768, sB = sA + 16384;
        #pragma unroll
        for (int ks = 0; ks < 4; ks++){
            unsigned a[4][4];
            #pragma unroll
            for (int mt = 0; mt < 4; mt++){
                int r = wm*64 + mt*16 + (lane & 15), c = ks*16 + (lane >> 4)*8;
                asm volatile("ldmatrix.sync.aligned.m8n8.x4.shared.b16 {%0,%1,%2,%3}, [%4];"
                    : "=r"(a[mt][0]),"=r"(a[mt][1]),"=r"(a[mt][2]),"=r"(a[mt][3])
                    : "r"(sA + swz(r*128 + c*2)));
            }
            #pragma unroll
            for (int nt = 0; nt < 4; nt++){
                int nb = wn*4 + nt;
                int panel = nb>>3, cip = nb&7;
                unsigned b2[2];
                int kk = ks*16 + (lane & 15);
                asm volatile("ldmatrix.sync.aligned.m8n8.x2.trans.shared.b16 {%0,%1}, [%2];"
                    : "=r"(b2[0]),"=r"(b2[1])
                    : "r"(sB + panel*8192 + swz(kk*128 + cip*16)));
                #pragma unroll
                for (int mt = 0; mt < 4; mt++){
                    float* d = acc[mt][nt];
                    asm volatile("mma.sync.aligned.m16n8k16.row.col.f32.bf16.bf16.f32 "
                        "{%0,%1,%2,%3}, {%4,%5,%6,%7}, {%8,%9}, {%0,%1,%2,%3};"
                        : "+f"(d[0]),"+f"(d[1]),"+f"(d[2]),"+f"(d[3])
                        : "r"(a[mt][0]),"r"(a[mt][1]),"r"(a[mt][2]),"r"(a[mt][3]),
                          "r"(b2[0]),"r"(b2[1]));
                }
            }
        }
        __syncthreads();
    }
    #pragma unroll
    for (int nt = 0; nt < 4; nt++){
        int c = col0 + wn*32 + nt*8 + (lane&3)*2;
        float bv0 = bias[c], bv1 = bias[c+1];
        #pragma unroll
        for (int mt = 0; mt < 4; mt++){
            int r = row0 + wm*64 + mt*16 + (lane>>2);
            if (r < 3136)
                *reinterpret_cast<__nv_bfloat162*>(&Cb[(long)r*16000 + c]) =
                    __floats2bfloat162_rn(acc[mt][nt][0]+bv0, acc[mt][nt][1]+bv1);
            if (r+8 < 3136)
                *reinterpret_cast<__nv_bfloat162*>(&Cb[(long)(r+8)*16000 + c]) =
                    __floats2bfloat162_rn(acc[mt][nt][2]+bv0, acc[mt][nt][3]+bv1);
        }
    }
}

// ---- fused attention (R6-proven): sums 4 q-partials, bf16 keys/eo ----
__global__ __launch_bounds__(256) void attention(
    const float* __restrict__ qpart, const __nv_bfloat16* __restrict__ keysb,
    const __nv_bfloat16* __restrict__ eob, __nv_bfloat16* __restrict__ ctxb,
    const float* __restrict__ b1, const float* __restrict__ V, const float* __restrict__ bV)
{
    __shared__ float qs[1024];
    __shared__ float Vs[1024];
    __shared__ float sc[64];
    const int b = blockIdx.x, tid = threadIdx.x, warp = tid>>5, lane = tid&31;
    const int QP = 65536;
    for (int u = tid; u < 1024; u += 256){
        long p = b*1024 + u;
        qs[u] = qpart[p] + qpart[QP+p] + qpart[2*QP+p] + qpart[3*QP+p] + b1[u];
        Vs[u] = V[u];
    }
    __syncthreads();
    for (int s = warp; s < 50; s += 8){
        const __nv_bfloat16* kr = keysb + (long)(b*50 + s)*1024;
        float a = 0.f;
        for (int u = lane*2; u < 1024; u += 64){
            __nv_bfloat162 k2 = *reinterpret_cast<const __nv_bfloat162*>(kr + u);
            a += Vs[u]   * tanha(qs[u]   + __bfloat162float(k2.x));
            a += Vs[u+1] * tanha(qs[u+1] + __bfloat162float(k2.y));
        }
        #pragma unroll
        for (int o = 16; o; o >>= 1) a += __shfl_xor_sync(0xffffffffu, a, o);
        if (lane == 0) sc[s] = a + bV[0];
    }
    __syncthreads();
    if (warp == 0){
        float v0 = sc[lane];
        bool has1 = (lane + 32) < 50;
        float v1 = has1 ? sc[lane + 32] : -1e30f;
        float m = fmaxf(v0, v1);
        #pragma unroll
        for (int o = 16; o; o >>= 1) m = fmaxf(m, __shfl_xor_sync(0xffffffffu, m, o));
        float e0 = __expf(v0 - m);
        float e1 = has1 ? __expf(v1 - m) : 0.f;
        float ssum = e0 + e1;
        #pragma unroll
        for (int o = 16; o; o >>= 1) ssum += __shfl_xor_sync(0xffffffffu, ssum, o);
        float inv = 1.0f / ssum;
        sc[lane] = e0 * inv;
        sc[lane + 32] = e1 * inv;
    }
    __syncthreads();
    for (int u0 = tid*2; u0 < 1024; u0 += 512){
        float a0 = 0.f, a1 = 0.f;
        const __nv_bfloat16* er = eob + (long)b*51200 + u0;
        #pragma unroll 10
        for (int s = 0; s < 50; s++){
            __nv_bfloat162 e2 = *reinterpret_cast<const __nv_bfloat162*>(er + (long)s*1024);
            a0 = fmaf(sc[s], __bfloat162float(e2.x), a0);
            a1 = fmaf(sc[s], __bfloat162float(e2.y), a1);
        }
        *reinterpret_cast<__nv_bfloat162*>(&ctxb[b*1024 + u0]) = __floats2bfloat162_rn(a0, a1);
    }
}

// ---- loss over bf16 logits ----
__global__ __launch_bounds__(256) void loss_kernel(
    const __nv_bfloat16* __restrict__ lg, const int* __restrict__ targ, float* __restrict__ nll)
{
    __shared__ float red[256];
    const int row = blockIdx.x, tid = threadIdx.x;
    const int t = row >> 6, b = row & 63;
    const __nv_bfloat16* lr = lg + (long)row*16000;
    float m = -1e30f;
    for (int j = tid*2; j < 16000; j += 512){
        __nv_bfloat162 p = *reinterpret_cast<const __nv_bfloat162*>(lr + j);
        m = fmaxf(m, fmaxf(__bfloat162float(p.x), __bfloat162float(p.y)));
    }
    red[tid] = m; __syncthreads();
    for (int o = 128; o; o >>= 1){ if (tid < o) red[tid] = fmaxf(red[tid], red[tid+o]); __syncthreads(); }
    m = red[0]; __syncthreads();
    float s = 0.f;
    for (int j = tid*2; j < 16000; j += 512){
        __nv_bfloat162 p = *reinterpret_cast<const __nv_bfloat162*>(lr + j);
        s += __expf(__bfloat162float(p.x) - m) + __expf(__bfloat162float(p.y) - m);
    }
    red[tid] = s; __syncthreads();
    for (int o = 128; o; o >>= 1){ if (tid < o) red[tid] += red[tid+o]; __syncthreads(); }
    if (tid == 0){
        int yt = targ[b*50 + t + 1];
        float lse = m + __logf(red[0]);
        nll[row] = (yt != 0) ? (lse - __bfloat162float(lr[yt])) * (1.0f/64.0f) : 0.f;
    }
}
__global__ __launch_bounds__(1024) void final_reduce(const float* __restrict__ nll, float* __restrict__ out){
    __shared__ float red[1024];
    int tid = threadIdx.x;
    float s = 0.f;
    for (int i = tid; i < 3136; i += 1024) s += nll[i];
    red[tid] = s; __syncthreads();
    for (int o = 512; o; o >>= 1){ if (tid < o) red[tid] += red[tid+o]; __syncthreads(); }
    if (tid == 0) out[0] = red[0];
}

extern "C" void kernel_launch(void* const* d_in, const int* in_sizes, int n_in,
                              void* d_out, int out_size) {
    const int*   inp     = (const int*)  d_in[0];
    const int*   targ    = (const int*)  d_in[1];
    const float* enc_hid = (const float*)d_in[2];
    const float* enc_emb = (const float*)d_in[3];
    const float* enc_Wx  = (const float*)d_in[4];
    const float* enc_Wh  = (const float*)d_in[5];
    const float* enc_b   = (const float*)d_in[6];
    const float* W1      = (const float*)d_in[7];
    const float* b1      = (const float*)d_in[8];
    const float* W2      = (const float*)d_in[9];
    const float* b2      = (const float*)d_in[10];
    const float* V       = (const float*)d_in[11];
    const float* bV      = (const float*)d_in[12];
    const float* dec_emb = (const float*)d_in[13];
    const float* dec_Wx  = (const float*)d_in[14];
    const float* dec_b   = (const float*)d_in[16];
    const float* fc_W    = (const float*)d_in[17];
    const float* fc_b    = (const float*)d_in[18];
    float* out = (float*)d_out;

    float* S; cudaGetSymbolAddress((void**)&S, g_scratch);
    int *didx, *eidx;
    cudaGetSymbolAddress((void**)&didx, g_didx);
    cudaGetSymbolAddress((void**)&eidx, g_eidx);
    __nv_bfloat16 *fcWb,*encWhb,*W1b,*decWxb,*decWxb2,*encWxb,*W2b,*encEmbb,*decEmbb;
    __nv_bfloat16 *h0,*h1,*ctxb,*eob,*keysb,*hallb,*logitsb;
    cudaGetSymbolAddress((void**)&fcWb,    g_fcWb);
    cudaGetSymbolAddress((void**)&encWhb,  g_encWhb);
    cudaGetSymbolAddress((void**)&W1b,     g_W1b);
    cudaGetSymbolAddress((void**)&decWxb,  g_decWxb);
    cudaGetSymbolAddress((void**)&decWxb2, g_decWxb2);
    cudaGetSymbolAddress((void**)&encWxb,  g_encWxb);
    cudaGetSymbolAddress((void**)&W2b,     g_W2b);
    cudaGetSymbolAddress((void**)&encEmbb, g_encEmbb);
    cudaGetSymbolAddress((void**)&decEmbb, g_decEmbb);
    cudaGetSymbolAddress((void**)&h0,      g_h0);
    cudaGetSymbolAddress((void**)&h1,      g_h1);
    cudaGetSymbolAddress((void**)&ctxb,    g_ctxb);
    cudaGetSymbolAddress((void**)&eob,     g_eob);
    cudaGetSymbolAddress((void**)&keysb,   g_keysb);
    cudaGetSymbolAddress((void**)&hallb,   g_hallb);
    cudaGetSymbolAddress((void**)&logitsb, g_logitsb);

    float* encgi = S + O_ENCGI;
    float* dembgi= S + O_DEMB;
    float* part  = S + O_PART;
    float* qpart = S + O_QPART;
    float* hf    = S + O_HF;
    float* nll   = S + O_NLL;

    cudaFuncSetAttribute(gemm_fc, cudaFuncAttributeMaxDynamicSharedMemorySize, 65536);

    setup_all<<<256, 256>>>(inp, targ, enc_hid, hf, h0);

    cvt_bf16<<<16000, 256>>>(fcWb,   fc_W,                16384000L);
    cvt_bf16<<<3072, 256>>>(encWhb,  enc_Wh,              3145728L);
    cvt_bf16<<<1024, 256>>>(W1b,     W1,                  1048576L);
    cvt_bf16<<<3072, 256>>>(decWxb,  dec_Wx,              3145728L);
    cvt_bf16<<<768,  256>>>(decWxb2, dec_Wx + 1024L*3072, 786432L);
    cvt_bf16<<<768,  256>>>(encWxb,  enc_Wx,              786432L);
    cvt_bf16<<<1024, 256>>>(W2b,     W2,                  1048576L);
    cvt_bf16<<<3000, 256>>>(encEmbb, enc_emb,             3072000L);
    cvt_bf16<<<4000, 256>>>(decEmbb, dec_emb,             4096000L);

    gemm_mma<<<dim3(48, 50), 256>>>(encEmbb, 256, eidx, encWxb,  3072, enc_b, encgi,  nullptr, 3072, 256);
    gemm_mma<<<dim3(48, 49), 256>>>(decEmbb, 256, didx, decWxb2, 3072, dec_b, dembgi, nullptr, 3072, 256);

    // encoder: ONE fused node per step (192 blocks, last-of-12 combine), h ping-pong
    for (int t = 0; t < 50; t++){
        __nv_bfloat16* hin  = (t & 1) ? h1 : h0;
        __nv_bfloat16* hout = (t & 1) ? h0 : h1;
        enc_step<<<dim3(48, 4), 256>>>(t, hin, encWhb, encgi, enc_b + 3072, part, hf, hout, eob);
    }
    __nv_bfloat16* hdec = h0;   // final write at t=49 (odd) lands in h0

    gemm_mma<<<dim3(16, 50), 256>>>(eob, 1024, nullptr, W2b, 1024, b2, nullptr, keysb, 1024, 1024);

    // decoder: 3 nodes/step
    for (int t = 0; t < 49; t++){
        gemm_splitk_q<<<dim3(16, 4), 256>>>(hdec, W1b, qpart);
        attention<<<64, 256>>>(qpart, keysb, eob, ctxb, b1, V, bV);
        dec_step<<<dim3(48, 4), 256>>>(t, ctxb, decWxb, dembgi, dec_b + 3072, part, hdec, hallb);
    }

    // batched fc logits, 128x128 tiles
    gemm_fc<<<dim3(125, 25), 256, 65536>>>(hallb, fcWb, fc_b, logitsb);

    loss_kernel<<<3136, 256>>>(logitsb, targ, nll);
    final_reduce<<<1, 1024>>>(nll, out);
}

// round 11
// speedup vs baseline: 2.1081x; 2.1081x over previous
#include <cuda_runtime.h>
#include <cuda_bf16.h>
#include <cstdint>

#define DEV __device__ __forceinline__
DEV float sigm(float x){ return 1.0f/(1.0f+__expf(-x)); }
DEV float ftanh(float x){ return 1.0f - 2.0f/(__expf(2.0f*x)+1.0f); }
DEV float tanha(float x){ float r; asm("tanh.approx.f32 %0, %1;" : "=f"(r) : "f"(x)); return r; }
DEV unsigned swz(unsigned off){ return off ^ ((off>>3)&0x70); }

// dims: B=64,S=50,T=50,U=1024,E=256,VT=16000,G3=3072
constexpr long O_ENCGI = 0;                      // 3200x3072 row=t*64+b
constexpr long O_DEMB  = O_ENCGI + 9830400L;     // 3136x3072 row=t*64+b
constexpr long O_PART  = O_DEMB  + 9633792L;     // 4 x 64x3072 split-K partials
constexpr long O_QPART = O_PART  + 786432L;      // 4 x 64x1024
constexpr long O_HF    = O_QPART + 262144L;      // 64x1024 f32 enc h
constexpr long O_NLL   = O_HF    + 65536L;       // 3136
constexpr long SCRATCH_TOTAL = O_NLL + 3200L;

__device__ __align__(16) float g_scratch[SCRATCH_TOTAL];
__device__ int g_didx[3136];
__device__ int g_eidx[3200];

__device__ __align__(16) __nv_bfloat16 g_fcWb[16384000];
__device__ __align__(16) __nv_bfloat16 g_encWhb[3145728];
__device__ __align__(16) __nv_bfloat16 g_W1b[1048576];
__device__ __align__(16) __nv_bfloat16 g_decWxb[3145728];
__device__ __align__(16) __nv_bfloat16 g_decWxb2[786432];
__device__ __align__(16) __nv_bfloat16 g_encWxb[786432];
__device__ __align__(16) __nv_bfloat16 g_W2b[1048576];
__device__ __align__(16) __nv_bfloat16 g_encEmbb[3072000];
__device__ __align__(16) __nv_bfloat16 g_decEmbb[4096000];
__device__ __align__(16) __nv_bfloat16 g_hb[65536];       // recurrent state (enc then dec)
__device__ __align__(16) __nv_bfloat16 g_ctxb[65536];
__device__ __align__(16) __nv_bfloat16 g_eob[3276800];    // row=b*50+t
__device__ __align__(16) __nv_bfloat16 g_keysb[3276800];  // row=b*50+t
__device__ __align__(16) __nv_bfloat16 g_hallb[3211264];  // row=t*64+b
__device__ __align__(16) __nv_bfloat16 g_logitsb[50176000];

__global__ void setup_all(const int* __restrict__ inp, const int* __restrict__ targ,
                          const float* __restrict__ hsrc, float* __restrict__ hf,
                          __nv_bfloat16* __restrict__ hb){
    int i = blockIdx.x*256 + threadIdx.x;
    if (i < 65536){ float v = hsrc[i]; hf[i] = v; hb[i] = __float2bfloat16(v); }
    if (i < 3136){ int t = i >> 6, b = i & 63; g_didx[i] = targ[b*50 + t]; }
    if (i < 3200){ int t = i >> 6, b = i & 63; g_eidx[i] = inp[b*50 + t]; }
}
__global__ void cvt_bf16(__nv_bfloat16* __restrict__ dst, const float* __restrict__ src, long n){
    long i = ((long)blockIdx.x*256 + threadIdx.x)*4;
    if (i < n){
        float4 v = *reinterpret_cast<const float4*>(src + i);
        __nv_bfloat162 lo = __floats2bfloat162_rn(v.x, v.y);
        __nv_bfloat162 hi = __floats2bfloat162_rn(v.z, v.w);
        uint2 o; o.x = *reinterpret_cast<unsigned*>(&lo); o.y = *reinterpret_cast<unsigned*>(&hi);
        *reinterpret_cast<uint2*>(dst + i) = o;
    }
}

// ---- general 64x64 mma GEMM, gather A, f32 and/or bf16 out (R6-proven) ----
__global__ __launch_bounds__(256) void gemm_mma(
    const __nv_bfloat16* __restrict__ A, int lda, const int* __restrict__ gidx,
    const __nv_bfloat16* __restrict__ Bm, int ldb, const float* __restrict__ bias,
    float* __restrict__ C, __nv_bfloat16* __restrict__ Cb, int ldc, int K)
{
    __shared__ __align__(16) char smA[2][8192];
    __shared__ __align__(16) char smB[2][8192];
    const int tid = threadIdx.x, warp = tid >> 5, lane = tid & 31;
    const int wm = warp >> 2, wn = warp & 3;
    const int row0 = blockIdx.y << 6, col0 = blockIdx.x << 6;
    unsigned sA[2] = { (unsigned)__cvta_generic_to_shared(smA[0]), (unsigned)__cvta_generic_to_shared(smA[1]) };
    unsigned sB[2] = { (unsigned)__cvta_generic_to_shared(smB[0]), (unsigned)__cvta_generic_to_shared(smB[1]) };
    float acc[2][2][4] = {};
    const int lr = tid >> 3, lc = tid & 7;
    long ar0 = gidx ? (long)gidx[row0+lr]*lda    : (long)(row0+lr)*lda;
    long ar1 = gidx ? (long)gidx[row0+lr+32]*lda : (long)(row0+lr+32)*lda;
    auto issue = [&](int st, int k0){
        asm volatile("cp.async.cg.shared.global [%0], [%1], 16;"
            :: "r"(sA[st] + swz(lr*128 + lc*16)), "l"(A + ar0 + k0 + lc*8));
        asm volatile("cp.async.cg.shared.global [%0], [%1], 16;"
            :: "r"(sA[st] + swz((lr+32)*128 + lc*16)), "l"(A + ar1 + k0 + lc*8));
        #pragma unroll
        for (int i=0;i<2;i++){
            int r = lr + i*32;
            asm volatile("cp.async.cg.shared.global [%0], [%1], 16;"
                :: "r"(sB[st] + swz(r*128 + lc*16)), "l"(Bm + (long)(k0+r)*ldb + col0 + lc*8));
        }
        asm volatile("cp.async.commit_group;");
    };
    const int nk = K >> 6;
    issue(0, 0);
    for (int kt = 0; kt < nk; kt++){
        if (kt + 1 < nk){ issue((kt+1)&1, (kt+1)<<6); asm volatile("cp.async.wait_group 1;" ::: "memory"); }
        else asm volatile("cp.async.wait_group 0;" ::: "memory");
        __syncthreads();
        const int st = kt & 1;
        #pragma unroll
        for (int ks = 0; ks < 4; ks++){
            unsigned a[2][4];
            #pragma unroll
            for (int mt = 0; mt < 2; mt++){
                int r = wm*32 + mt*16 + (lane & 15), c = ks*16 + (lane >> 4)*8;
                asm volatile("ldmatrix.sync.aligned.m8n8.x4.shared.b16 {%0,%1,%2,%3}, [%4];"
                    : "=r"(a[mt][0]),"=r"(a[mt][1]),"=r"(a[mt][2]),"=r"(a[mt][3])
                    : "r"(sA[st] + swz(r*128 + c*2)));
            }
            unsigned b[4];
            int kk = ks*16 + ((lane>>3)&1)*8 + (lane & 7), nn = wn*16 + (lane>>4)*8;
            asm volatile("ldmatrix.sync.aligned.m8n8.x4.trans.shared.b16 {%0,%1,%2,%3}, [%4];"
                : "=r"(b[0]),"=r"(b[1]),"=r"(b[2]),"=r"(b[3])
                : "r"(sB[st] + swz(kk*128 + nn*2)));
            #pragma unroll
            for (int mt = 0; mt < 2; mt++)
                #pragma unroll
                for (int nt = 0; nt < 2; nt++){
                    float* d = acc[mt][nt];
                    asm volatile("mma.sync.aligned.m16n8k16.row.col.f32.bf16.bf16.f32 "
                        "{%0,%1,%2,%3}, {%4,%5,%6,%7}, {%8,%9}, {%0,%1,%2,%3};"
                        : "+f"(d[0]),"+f"(d[1]),"+f"(d[2]),"+f"(d[3])
                        : "r"(a[mt][0]),"r"(a[mt][1]),"r"(a[mt][2]),"r"(a[mt][3]),
                          "r"(b[nt*2]),"r"(b[nt*2+1]));
                }
        }
        __syncthreads();
    }
    const int rb = row0 + wm*32 + (lane>>2), cb = col0 + wn*16 + (lane&3)*2;
    #pragma unroll
    for (int nt = 0; nt < 2; nt++){
        int cc = cb + nt*8;
        float bv0 = bias ? bias[cc] : 0.f, bv1 = bias ? bias[cc+1] : 0.f;
        #pragma unroll
        for (int mt = 0; mt < 2; mt++){
            int r = rb + mt*16;
            float x0 = acc[mt][nt][0]+bv0, x1 = acc[mt][nt][1]+bv1;
            float y0 = acc[mt][nt][2]+bv0, y1 = acc[mt][nt][3]+bv1;
            if (C){
                *reinterpret_cast<float2*>(&C[(long)r*ldc + cc]) = make_float2(x0, x1);
                *reinterpret_cast<float2*>(&C[(long)(r+8)*ldc + cc]) = make_float2(y0, y1);
            }
            if (Cb){
                *reinterpret_cast<__nv_bfloat162*>(&Cb[(long)r*ldc + cc]) = __floats2bfloat162_rn(x0, x1);
                *reinterpret_cast<__nv_bfloat162*>(&Cb[(long)(r+8)*ldc + cc]) = __floats2bfloat162_rn(y0, y1);
            }
        }
    }
}

// ---- split-K skinny GEMM: M=64 fixed, grid (N/64, KS); partial z -> C + z*64*N ----
__global__ __launch_bounds__(256) void gemm_splitk(
    const __nv_bfloat16* __restrict__ A, int lda,
    const __nv_bfloat16* __restrict__ Bm, int ldb,
    float* __restrict__ C, int N, int K, int KS)
{
    __shared__ __align__(16) char smA[2][8192];
    __shared__ __align__(16) char smB[2][8192];
    const int tid = threadIdx.x, warp = tid >> 5, lane = tid & 31;
    const int wm = warp >> 2, wn = warp & 3;
    const int col0 = blockIdx.x << 6;
    const int kbeg = blockIdx.y * (K / KS);
    unsigned sA[2] = { (unsigned)__cvta_generic_to_shared(smA[0]), (unsigned)__cvta_generic_to_shared(smA[1]) };
    unsigned sB[2] = { (unsigned)__cvta_generic_to_shared(smB[0]), (unsigned)__cvta_generic_to_shared(smB[1]) };
    float acc[2][2][4] = {};
    const int lr = tid >> 3, lc = tid & 7;
    auto issue = [&](int st, int k0){
        asm volatile("cp.async.cg.shared.global [%0], [%1], 16;"
            :: "r"(sA[st] + swz(lr*128 + lc*16)), "l"(A + (long)lr*lda + kbeg + k0 + lc*8));
        asm volatile("cp.async.cg.shared.global [%0], [%1], 16;"
            :: "r"(sA[st] + swz((lr+32)*128 + lc*16)), "l"(A + (long)(lr+32)*lda + kbeg + k0 + lc*8));
        #pragma unroll
        for (int i=0;i<2;i++){
            int r = lr + i*32;
            asm volatile("cp.async.cg.shared.global [%0], [%1], 16;"
                :: "r"(sB[st] + swz(r*128 + lc*16)), "l"(Bm + (long)(kbeg+k0+r)*ldb + col0 + lc*8));
        }
        asm volatile("cp.async.commit_group;");
    };
    const int nk = (K / KS) >> 6;
    issue(0, 0);
    for (int kt = 0; kt < nk; kt++){
        if (kt + 1 < nk){ issue((kt+1)&1, (kt+1)<<6); asm volatile("cp.async.wait_group 1;" ::: "memory"); }
        else asm volatile("cp.async.wait_group 0;" ::: "memory");
        __syncthreads();
        const int st = kt & 1;
        #pragma unroll
        for (int ks = 0; ks < 4; ks++){
            unsigned a[2][4];
            #pragma unroll
            for (int mt = 0; mt < 2; mt++){
                int r = wm*32 + mt*16 + (lane & 15), c = ks*16 + (lane >> 4)*8;
                asm volatile("ldmatrix.sync.aligned.m8n8.x4.shared.b16 {%0,%1,%2,%3}, [%4];"
                    : "=r"(a[mt][0]),"=r"(a[mt][1]),"=r"(a[mt][2]),"=r"(a[mt][3])
                    : "r"(sA[st] + swz(r*128 + c*2)));
            }
            unsigned b[4];
            int kk = ks*16 + ((lane>>3)&1)*8 + (lane & 7), nn = wn*16 + (lane>>4)*8;
            asm volatile("ldmatrix.sync.aligned.m8n8.x4.trans.shared.b16 {%0,%1,%2,%3}, [%4];"
                : "=r"(b[0]),"=r"(b[1]),"=r"(b[2]),"=r"(b[3])
                : "r"(sB[st] + swz(kk*128 + nn*2)));
            #pragma unroll
            for (int mt = 0; mt < 2; mt++)
                #pragma unroll
                for (int nt = 0; nt < 2; nt++){
                    float* d = acc[mt][nt];
                    asm volatile("mma.sync.aligned.m16n8k16.row.col.f32.bf16.bf16.f32 "
                        "{%0,%1,%2,%3}, {%4,%5,%6,%7}, {%8,%9}, {%0,%1,%2,%3};"
                        : "+f"(d[0]),"+f"(d[1]),"+f"(d[2]),"+f"(d[3])
                        : "r"(a[mt][0]),"r"(a[mt][1]),"r"(a[mt][2]),"r"(a[mt][3]),
                          "r"(b[nt*2]),"r"(b[nt*2+1]));
                }
        }
        __syncthreads();
    }
    float* Cout = C + (long)blockIdx.y * 64 * N;
    const int rb = wm*32 + (lane>>2), cb = col0 + wn*16 + (lane&3)*2;
    #pragma unroll
    for (int nt = 0; nt < 2; nt++){
        int cc = cb + nt*8;
        #pragma unroll
        for (int mt = 0; mt < 2; mt++){
            int r = rb + mt*16;
            *reinterpret_cast<float2*>(&Cout[(long)r*N + cc]) = make_float2(acc[mt][nt][0], acc[mt][nt][1]);
            *reinterpret_cast<float2*>(&Cout[(long)(r+8)*N + cc]) = make_float2(acc[mt][nt][2], acc[mt][nt][3]);
        }
    }
}

// ---- encoder GRU combine: sum 4 partials + gates + state update ----
__global__ __launch_bounds__(256) void enc_combine(
    int t, const float* __restrict__ encgi, const float* __restrict__ part,
    const float* __restrict__ encb2,
    float* __restrict__ hf, __nv_bfloat16* __restrict__ hb, __nv_bfloat16* __restrict__ eob)
{
    const int PS = 64*3072;
    int i = blockIdx.x*256 + threadIdx.x;
    int b = i >> 10, u = i & 1023;
    long p = (long)b*3072 + u;
    long gi = (long)(t*64 + b)*3072 + u;
    float ghz = part[p]      + part[PS+p]      + part[2*PS+p]      + part[3*PS+p]      + encb2[u];
    float ghr = part[p+1024] + part[PS+p+1024] + part[2*PS+p+1024] + part[3*PS+p+1024] + encb2[1024+u];
    float ghh = part[p+2048] + part[PS+p+2048] + part[2*PS+p+2048] + part[3*PS+p+2048] + encb2[2048+u];
    float z = sigm(encgi[gi] + ghz);
    float r = sigm(encgi[gi+1024] + ghr);
    float hc = ftanh(encgi[gi+2048] + r*ghh);
    float hn = z*hf[i] + (1.0f - z)*hc;
    hf[i] = hn;
    hb[i] = __float2bfloat16(hn);
    eob[(long)(b*50 + t)*1024 + u] = __float2bfloat16(hn);
}

// ---- decoder GRU combine (h==0) ----
__global__ __launch_bounds__(256) void dec_combine(
    int t, const float* __restrict__ dembgi, const float* __restrict__ part,
    const float* __restrict__ decb2,
    __nv_bfloat16* __restrict__ hb, __nv_bfloat16* __restrict__ hallb)
{
    const int PS = 64*3072;
    int i = blockIdx.x*256 + threadIdx.x;
    int b = i >> 10, u = i & 1023;
    long p = (long)b*3072 + u;
    long gi = (long)(t*64 + b)*3072 + u;
    float gz = part[p]      + part[PS+p]      + part[2*PS+p]      + part[3*PS+p];
    float gr = part[p+1024] + part[PS+p+1024] + part[2*PS+p+1024] + part[3*PS+p+1024];
    float gh = part[p+2048] + part[PS+p+2048] + part[2*PS+p+2048] + part[3*PS+p+2048];
    float z = sigm(dembgi[gi] + gz + decb2[u]);
    float r = sigm(dembgi[gi+1024] + gr + decb2[1024+u]);
    float hc = ftanh(dembgi[gi+2048] + gh + r*decb2[2048+u]);
    float hn = (1.0f - z)*hc;
    __nv_bfloat16 hv = __float2bfloat16(hn);
    hb[i] = hv;
    hallb[(long)(t*64 + b)*1024 + u] = hv;
}

// ---- fused attention: sum 4 q-partials, scores (tanh.approx), softmax, ctx; bf16 keys/eo ----
__global__ __launch_bounds__(256) void attention(
    const float* __restrict__ qpart, const __nv_bfloat16* __restrict__ keysb,
    const __nv_bfloat16* __restrict__ eob, __nv_bfloat16* __restrict__ ctxb,
    const float* __restrict__ b1, const float* __restrict__ V, const float* __restrict__ bV)
{
    __shared__ float qs[1024];
    __shared__ float Vs[1024];
    __shared__ float sc[64];
    const int b = blockIdx.x, tid = threadIdx.x, warp = tid>>5, lane = tid&31;
    const int QP = 65536;
    for (int u = tid; u < 1024; u += 256){
        long p = b*1024 + u;
        qs[u] = qpart[p] + qpart[QP+p] + qpart[2*QP+p] + qpart[3*QP+p] + b1[u];
        Vs[u] = V[u];
    }
    __syncthreads();
    for (int s = warp; s < 50; s += 8){
        const __nv_bfloat16* kr = keysb + (long)(b*50 + s)*1024;
        float a = 0.f;
        for (int u = lane*2; u < 1024; u += 64){
            __nv_bfloat162 k2 = *reinterpret_cast<const __nv_bfloat162*>(kr + u);
            a += Vs[u]   * tanha(qs[u]   + __bfloat162float(k2.x));
            a += Vs[u+1] * tanha(qs[u+1] + __bfloat162float(k2.y));
        }
        #pragma unroll
        for (int o = 16; o; o >>= 1) a += __shfl_xor_sync(0xffffffffu, a, o);
        if (lane == 0) sc[s] = a + bV[0];
    }
    __syncthreads();
    if (warp == 0){
        float v0 = sc[lane];
        bool has1 = (lane + 32) < 50;
        float v1 = has1 ? sc[lane + 32] : -1e30f;
        float m = fmaxf(v0, v1);
        #pragma unroll
        for (int o = 16; o; o >>= 1) m = fmaxf(m, __shfl_xor_sync(0xffffffffu, m, o));
        float e0 = __expf(v0 - m);
        float e1 = has1 ? __expf(v1 - m) : 0.f;
        float ssum = e0 + e1;
        #pragma unroll
        for (int o = 16; o; o >>= 1) ssum += __shfl_xor_sync(0xffffffffu, ssum, o);
        float inv = 1.0f / ssum;
        sc[lane] = e0 * inv;
        sc[lane + 32] = e1 * inv;
    }
    __syncthreads();
    for (int u0 = tid*2; u0 < 1024; u0 += 512){
        float a0 = 0.f, a1 = 0.f;
        const __nv_bfloat16* er = eob + (long)b*51200 + u0;
        #pragma unroll 10
        for (int s = 0; s < 50; s++){
            __nv_bfloat162 e2 = *reinterpret_cast<const __nv_bfloat162*>(er + (long)s*1024);
            a0 = fmaf(sc[s], __bfloat162float(e2.x), a0);
            a1 = fmaf(sc[s], __bfloat162float(e2.y), a1);
        }
        *reinterpret_cast<__nv_bfloat162*>(&ctxb[b*1024 + u0]) = __floats2bfloat162_rn(a0, a1);
    }
}

// ---- fc GEMM: BM=128 BN=128 BK=64, bf16 out (verified bit-exact in R9) ----
__global__ __launch_bounds__(256) void gemm_fc(
    const __nv_bfloat16* __restrict__ A, const __nv_bfloat16* __restrict__ Bm,
    const float* __restrict__ bias, __nv_bfloat16* __restrict__ Cb)
{
    extern __shared__ char sm[];
    const int tid = threadIdx.x, warp = tid >> 5, lane = tid & 31;
    const int wm = warp >> 2, wn = warp & 3;
    const int row0 = blockIdx.y << 7, col0 = blockIdx.x << 7;
    unsigned base = (unsigned)__cvta_generic_to_shared(sm);
    float acc[4][4][4] = {};
    auto issue = [&](int st, int k0){
        unsigned sA = base + st*32768, sB = sA + 16384;
        int r = tid>>3, c8 = tid&7;
        #pragma unroll
        for (int i=0;i<4;i++){
            int rr = r + i*32;
            int rg = row0 + rr; if (rg > 3135) rg = 3135;
            asm volatile("cp.async.cg.shared.global [%0], [%1], 16;"
                :: "r"(sA + swz(rr*128 + c8*16)), "l"(A + (long)rg*1024 + k0 + c8*8));
        }
        #pragma unroll
        for (int p=0;p<4;p++){
            int idx = p*256 + tid;
            int rr = idx>>4, c16 = idx&15;
            int panel = c16>>3, cp = c16&7;
            asm volatile("cp.async.cg.shared.global [%0], [%1], 16;"
                :: "r"(sB + panel*8192 + swz(rr*128 + cp*16)),
                   "l"(Bm + (long)(k0+rr)*16000 + col0 + c16*8));
        }
        asm volatile("cp.async.commit_group;");
    };
    issue(0, 0);
    for (int kt = 0; kt < 16; kt++){
        if (kt+1 < 16){ issue((kt+1)&1, (kt+1)<<6); asm volatile("cp.async.wait_group 1;" ::: "memory"); }
        else asm volatile("cp.async.wait_group 0;" ::: "memory");
        __syncthreads();
        unsigned sA = base + (kt&1)*32768, sB = sA + 16384;
        #pragma unroll
        for (int ks = 0; ks < 4; ks++){
            unsigned a[4][4];
            #pragma unroll
            for (int mt = 0; mt < 4; mt++){
                int r = wm*64 + mt*16 + (lane & 15), c = ks*16 + (lane >> 4)*8;
                asm volatile("ldmatrix.sync.aligned.m8n8.x4.shared.b16 {%0,%1,%2,%3}, [%4];"
                    : "=r"(a[mt][0]),"=r"(a[mt][1]),"=r"(a[mt][2]),"=r"(a[mt][3])
                    : "r"(sA + swz(r*128 + c*2)));
            }
            #pragma unroll
            for (int nt = 0; nt < 4; nt++){
                int nb = wn*4 + nt;
                int panel = nb>>3, cip = nb&7;
                unsigned b2[2];
                int kk = ks*16 + (lane & 15);
                asm volatile("ldmatrix.sync.aligned.m8n8.x2.trans.shared.b16 {%0,%1}, [%2];"
                    : "=r"(b2[0]),"=r"(b2[1])
                    : "r"(sB + panel*8192 + swz(kk*128 + cip*16)));
                #pragma unroll
                for (int mt = 0; mt < 4; mt++){
                    float* d = acc[mt][nt];
                    asm volatile("mma.sync.aligned.m16n8k16.row.col.f32.bf16.bf16.f32 "
                        "{%0,%1,%2,%3}, {%4,%5,%6,%7}, {%8,%9}, {%0,%1,%2,%3};"
                        : "+f"(d[0]),"+f"(d[1]),"+f"(d[2]),"+f"(d[3])
                        : "r"(a[mt][0]),"r"(a[mt][1]),"r"(a[mt][2]),"r"(a[mt][3]),
                          "r"(b2[0]),"r"(b2[1]));
                }
            }
        }
        __syncthreads();
    }
    #pragma unroll
    for (int nt = 0; nt < 4; nt++){
        int c = col0 + wn*32 + nt*8 + (lane&3)*2;
        float bv0 = bias[c], bv1 = bias[c+1];
        #pragma unroll
        for (int mt = 0; mt < 4; mt++){
            int r = row0 + wm*64 + mt*16 + (lane>>2);
            if (r < 3136)
                *reinterpret_cast<__nv_bfloat162*>(&Cb[(long)r*16000 + c]) =
                    __floats2bfloat162_rn(acc[mt][nt][0]+bv0, acc[mt][nt][1]+bv1);
            if (r+8 < 3136)
                *reinterpret_cast<__nv_bfloat162*>(&Cb[(long)(r+8)*16000 + c]) =
                    __floats2bfloat162_rn(acc[mt][nt][2]+bv0, acc[mt][nt][3]+bv1);
        }
    }
}

// ---- loss over bf16 logits ----
__global__ __launch_bounds__(256) void loss_kernel(
    const __nv_bfloat16* __restrict__ lg, const int* __restrict__ targ, float* __restrict__ nll)
{
    __shared__ float red[256];
    const int row = blockIdx.x, tid = threadIdx.x;
    const int t = row >> 6, b = row & 63;
    const __nv_bfloat16* lr = lg + (long)row*16000;
    float m = -1e30f;
    for (int j = tid*2; j < 16000; j += 512){
        __nv_bfloat162 p = *reinterpret_cast<const __nv_bfloat162*>(lr + j);
        m = fmaxf(m, fmaxf(__bfloat162float(p.x), __bfloat162float(p.y)));
    }
    red[tid] = m; __syncthreads();
    for (int o = 128; o; o >>= 1){ if (tid < o) red[tid] = fmaxf(red[tid], red[tid+o]); __syncthreads(); }
    m = red[0]; __syncthreads();
    float s = 0.f;
    for (int j = tid*2; j < 16000; j += 512){
        __nv_bfloat162 p = *reinterpret_cast<const __nv_bfloat162*>(lr + j);
        s += __expf(__bfloat162float(p.x) - m) + __expf(__bfloat162float(p.y) - m);
    }
    red[tid] = s; __syncthreads();
    for (int o = 128; o; o >>= 1){ if (tid < o) red[tid] += red[tid+o]; __syncthreads(); }
    if (tid == 0){
        int yt = targ[b*50 + t + 1];
        float lse = m + __logf(red[0]);
        nll[row] = (yt != 0) ? (lse - __bfloat162float(lr[yt])) * (1.0f/64.0f) : 0.f;
    }
}
__global__ __launch_bounds__(1024) void final_reduce(const float* __restrict__ nll, float* __restrict__ out){
    __shared__ float red[1024];
    int tid = threadIdx.x;
    float s = 0.f;
    for (int i = tid; i < 3136; i += 1024) s += nll[i];
    red[tid] = s; __syncthreads();
    for (int o = 512; o; o >>= 1){ if (tid < o) red[tid] += red[tid+o]; __syncthreads(); }
    if (tid == 0) out[0] = red[0];
}

extern "C" void kernel_launch(void* const* d_in, const int* in_sizes, int n_in,
                              void* d_out, int out_size) {
    const int*   inp     = (const int*)  d_in[0];
    const int*   targ    = (const int*)  d_in[1];
    const float* enc_hid = (const float*)d_in[2];
    const float* enc_emb = (const float*)d_in[3];
    const float* enc_Wx  = (const float*)d_in[4];
    const float* enc_Wh  = (const float*)d_in[5];
    const float* enc_b   = (const float*)d_in[6];
    const float* W1      = (const float*)d_in[7];
    const float* b1      = (const float*)d_in[8];
    const float* W2      = (const float*)d_in[9];
    const float* b2      = (const float*)d_in[10];
    const float* V       = (const float*)d_in[11];
    const float* bV      = (const float*)d_in[12];
    const float* dec_emb = (const float*)d_in[13];
    const float* dec_Wx  = (const float*)d_in[14];
    const float* dec_b   = (const float*)d_in[16];
    const float* fc_W    = (const float*)d_in[17];
    const float* fc_b    = (const float*)d_in[18];
    float* out = (float*)d_out;

    float* S; cudaGetSymbolAddress((void**)&S, g_scratch);
    int *didx, *eidx;
    cudaGetSymbolAddress((void**)&didx, g_didx);
    cudaGetSymbolAddress((void**)&eidx, g_eidx);
    __nv_bfloat16 *fcWb,*encWhb,*W1b,*decWxb,*decWxb2,*encWxb,*W2b,*encEmbb,*decEmbb;
    __nv_bfloat16 *hb,*ctxb,*eob,*keysb,*hallb,*logitsb;
    cudaGetSymbolAddress((void**)&fcWb,    g_fcWb);
    cudaGetSymbolAddress((void**)&encWhb,  g_encWhb);
    cudaGetSymbolAddress((void**)&W1b,     g_W1b);
    cudaGetSymbolAddress((void**)&decWxb,  g_decWxb);
    cudaGetSymbolAddress((void**)&decWxb2, g_decWxb2);
    cudaGetSymbolAddress((void**)&encWxb,  g_encWxb);
    cudaGetSymbolAddress((void**)&W2b,     g_W2b);
    cudaGetSymbolAddress((void**)&encEmbb, g_encEmbb);
    cudaGetSymbolAddress((void**)&decEmbb, g_decEmbb);
    cudaGetSymbolAddress((void**)&hb,      g_hb);
    cudaGetSymbolAddress((void**)&ctxb,    g_ctxb);
    cudaGetSymbolAddress((void**)&eob,     g_eob);
    cudaGetSymbolAddress((void**)&keysb,   g_keysb);
    cudaGetSymbolAddress((void**)&hallb,   g_hallb);
    cudaGetSymbolAddress((void**)&logitsb, g_logitsb);

    float* encgi = S + O_ENCGI;
    float* dembgi= S + O_DEMB;
    float* part  = S + O_PART;
    float* qpart = S + O_QPART;
    float* hf    = S + O_HF;
    float* nll   = S + O_NLL;

    cudaFuncSetAttribute(gemm_fc, cudaFuncAttributeMaxDynamicSharedMemorySize, 65536);

    setup_all<<<256, 256>>>(inp, targ, enc_hid, hf, hb);

    cvt_bf16<<<16000, 256>>>(fcWb,   fc_W,                16384000L);
    cvt_bf16<<<3072, 256>>>(encWhb,  enc_Wh,              3145728L);
    cvt_bf16<<<1024, 256>>>(W1b,     W1,                  1048576L);
    cvt_bf16<<<3072, 256>>>(decWxb,  dec_Wx,              3145728L);
    cvt_bf16<<<768,  256>>>(decWxb2, dec_Wx + 1024L*3072, 786432L);
    cvt_bf16<<<768,  256>>>(encWxb,  enc_Wx,              786432L);
    cvt_bf16<<<1024, 256>>>(W2b,     W2,                  1048576L);
    cvt_bf16<<<3000, 256>>>(encEmbb, enc_emb,             3072000L);
    cvt_bf16<<<4000, 256>>>(decEmbb, dec_emb,             4096000L);

    // hoisted input-side GEMMs
    gemm_mma<<<dim3(48, 50), 256>>>(encEmbb, 256, eidx, encWxb,  3072, enc_b, encgi,  nullptr, 3072, 256);
    gemm_mma<<<dim3(48, 49), 256>>>(decEmbb, 256, didx, decWxb2, 3072, dec_b, dembgi, nullptr, 3072, 256);

    // encoder: split-K gemm (192 blocks) + combine, per step
    for (int t = 0; t < 50; t++){
        gemm_splitk<<<dim3(48, 4), 256>>>(hb, 1024, encWhb, 3072, part, 3072, 1024, 4);
        enc_combine<<<256, 256>>>(t, encgi, part, enc_b + 3072, hf, hb, eob);
    }

    // keys = enc_out @ W2 + b2 (bf16 out, row = b*50+t)
    gemm_mma<<<dim3(16, 50), 256>>>(eob, 1024, nullptr, W2b, 1024, b2, nullptr, keysb, 1024, 1024);

    // decoder: q split-K + fused attention + gates split-K + combine
    for (int t = 0; t < 49; t++){
        gemm_splitk<<<dim3(16, 4), 256>>>(hb, 1024, W1b, 1024, qpart, 1024, 1024, 4);
        attention<<<64, 256>>>(qpart, keysb, eob, ctxb, b1, V, bV);
        gemm_splitk<<<dim3(48, 4), 256>>>(ctxb, 1024, decWxb, 3072, part, 3072, 1024, 4);
        dec_combine<<<256, 256>>>(t, dembgi, part, dec_b + 3072, hb, hallb);
    }

    // batched fc logits, 128x128 tiles (bf16 out)
    gemm_fc<<<dim3(125, 25), 256, 65536>>>(hallb, fcWb, fc_b, logitsb);

    loss_kernel<<<3136, 256>>>(logitsb, targ, nll);
    final_reduce<<<1, 1024>>>(nll, out);
}